// round 9
// baseline (speedup 1.0000x reference)
#include <cuda_runtime.h>
#include <math.h>
#include <stdint.h>

#define NTOT 32768
#define HTOT 32
#define D    64
#define NT   128
#define NTHREADS 512
#define TILE_BYTES (NT * D * 4)   // 32768

// ---------- tf32 helpers ----------
__device__ __forceinline__ uint32_t f2tf32(float f) {
    uint32_t u;
    asm("cvt.rna.tf32.f32 %0, %1;" : "=r"(u) : "f"(f));
    return u;
}

__device__ __forceinline__ void mma_tf32(float& c0, float& c1, float& c2, float& c3,
                                         uint32_t a0, uint32_t a1, uint32_t a2, uint32_t a3,
                                         uint32_t b0, uint32_t b1) {
    asm volatile(
        "mma.sync.aligned.m16n8k8.row.col.f32.tf32.tf32.f32 "
        "{%0,%1,%2,%3}, {%4,%5,%6,%7}, {%8,%9}, {%0,%1,%2,%3};"
        : "+f"(c0), "+f"(c1), "+f"(c2), "+f"(c3)
        : "r"(a0), "r"(a1), "r"(a2), "r"(a3), "r"(b0), "r"(b1));
}

// tanh for |x| <~ 0.5 via odd polynomial
__device__ __forceinline__ float poly_tanh(float x) {
    float t = x * x;
    float p = fmaf(t, -0.05396825397f, 0.13333333333f);
    p = fmaf(t, p, -0.33333333333f);
    return fmaf(x * t, p, x);
}

// log-map-at-origin scale: 2*atanh(u)/u with u^2 = c*ssq (series)
__device__ __forceinline__ float logscale_from_ssq(float ssq, float c) {
    float t = c * ssq;
    float p = fmaf(t, 0.22222222f, 0.28571429f);
    p = fmaf(t, p, 0.4f);
    p = fmaf(t, p, 0.66666667f);
    return fmaf(t, p, 2.0f);
}

// Fragment-native swizzled tile layout (conflict-free; rounds 3-7).
__device__ __forceinline__ int chunk_off(int token, int ci, int j) {
    int pb = (token >> 1) & 1;
    int b2 = (token >> 2) & 1;
    int jl = j & 1;
    int j1 = (j >> 1) & 1;
    int slot = ((token & 1) << 2) | (ci ^ (jl ^ pb) ^ ((j1 ^ b2) << 1));
    return ((token >> 1) << 7) | (j << 5) | (slot << 2);
}

// ---------- TMA bulk copy + mbarrier ----------
__device__ __forceinline__ void mbar_init(uint32_t mbar, uint32_t cnt) {
    asm volatile("mbarrier.init.shared.b64 [%0], %1;" :: "r"(mbar), "r"(cnt) : "memory");
}
__device__ __forceinline__ void mbar_expect_tx(uint32_t mbar, uint32_t bytes) {
    asm volatile("mbarrier.arrive.expect_tx.shared.b64 _, [%0], %1;"
                 :: "r"(mbar), "r"(bytes) : "memory");
}
__device__ __forceinline__ void bulk_ld(uint32_t sdst, const void* gsrc, uint32_t mbar) {
    asm volatile(
        "cp.async.bulk.shared::cta.global.mbarrier::complete_tx::bytes [%0], [%1], %2, [%3];"
        :: "r"(sdst), "l"(gsrc), "r"((uint32_t)TILE_BYTES), "r"(mbar) : "memory");
}
__device__ __forceinline__ void mbar_wait(uint32_t mbar, uint32_t parity) {
    uint32_t done;
    asm volatile(
        "{\n\t.reg .pred p;\n\t"
        "mbarrier.try_wait.parity.acquire.cta.shared::cta.b64 p, [%1], %2;\n\t"
        "selp.b32 %0, 1, 0, p;\n\t}"
        : "=r"(done) : "r"(mbar), "r"(parity) : "memory");
    if (!done) {
        asm volatile(
            "{\n\t.reg .pred P1;\n\t"
            "WAIT_LOOP_%=:\n\t"
            "mbarrier.try_wait.parity.acquire.cta.shared::cta.b64 P1, [%0], %1, 0x989680;\n\t"
            "@P1 bra.uni WAIT_DONE_%=;\n\t"
            "bra.uni WAIT_LOOP_%=;\n\t"
            "WAIT_DONE_%=:\n\t}"
            :: "r"(mbar), "r"(parity) : "memory");
    }
}

// staging (raw fp32 rows) -> swizzled scaled tf32 tile, norms via 16-lane shfl
__device__ __forceinline__ void transform_tile(const float* __restrict__ stag,
                                               uint32_t* __restrict__ tileU,
                                               int t, float c) {
    const float4* s4 = reinterpret_cast<const float4*>(stag);
    const int col4 = t & 15;
    const int rgrp = t >> 4;          // 0..31
    const int j    = col4 >> 2;
    const int posR = col4 & 3;
    const int posP = posR ^ ((j & 1) << 1);
    int base[4];
    #pragma unroll
    for (int ci = 0; ci < 4; ci++)
        base[ci] = chunk_off(rgrp, ci, j) + posP;

    float4 v[4];
    float  ss[4];
    #pragma unroll
    for (int jj = 0; jj < 4; jj++) v[jj] = s4[t + 512 * jj];
    #pragma unroll
    for (int jj = 0; jj < 4; jj++) {
        float s = fmaf(v[jj].x, v[jj].x, fmaf(v[jj].y, v[jj].y,
                  fmaf(v[jj].z, v[jj].z, v[jj].w * v[jj].w)));
        #pragma unroll
        for (int off = 1; off < 16; off <<= 1)
            s += __shfl_xor_sync(0xffffffffu, s, off);
        ss[jj] = s;
    }
    #pragma unroll
    for (int jj = 0; jj < 4; jj++) {
        float sc = logscale_from_ssq(ss[jj], c);
        int o = jj << 11;               // +32 rows = +2048 floats
        tileU[base[0] + o] = f2tf32(v[jj].x * sc);
        tileU[base[1] + o] = f2tf32(v[jj].y * sc);
        tileU[base[2] + o] = f2tf32(v[jj].z * sc);
        tileU[base[3] + o] = f2tf32(v[jj].w * sc);
    }
}

__global__ __launch_bounds__(NTHREADS, 1)
void hyp_attn_kernel(const float* __restrict__ cur,
                     const float* __restrict__ hist,
                     const float* __restrict__ curv,
                     const float* __restrict__ Wq,
                     const float* __restrict__ bq,
                     const float* __restrict__ Wk,
                     const float* __restrict__ bk,
                     const float* __restrict__ av,
                     float* __restrict__ out) {
    extern __shared__ float sm[];
    uint32_t* tileU = reinterpret_cast<uint32_t*>(sm);   // 8192 u32
    float* stagA = sm + 8192;                            // 8192
    float* stagB = sm + 16384;                           // 8192
    float4* qfS  = reinterpret_cast<float4*>(sm + 24576);// 2048 float4 = 8192 fl
    float* lp    = sm + 32768;                           // 256
    uint32_t mbarBase = (uint32_t)__cvta_generic_to_shared(sm + 33024);

    const int t    = threadIdx.x;
    const int lane = t & 31;
    const int w    = t >> 5;          // 0..15
    const int n0   = blockIdx.x * NT;
    const float c  = curv[0];
    const float sc = sqrtf(c);

    const uint32_t mbar0 = mbarBase;
    const uint32_t mbar1 = mbarBase + 8;
    const uint32_t stAu = (uint32_t)__cvta_generic_to_shared(stagA);
    const uint32_t stBu = (uint32_t)__cvta_generic_to_shared(stagB);

    // warp roles: token-group w&7 (16 tokens), e-half w>>3 (32 e)
    const int tg = w & 7;
    const int eh = w >> 3;
    const int Tg = tg * 16;
    const int E0 = eh * 32;
    const int lr = lane >> 2;       // 0..7
    const int ci = lane & 3;

    // A-fragment chunk offsets for token Tg+lr; token Tg+lr+8 is +512
    int fbA[4];
    #pragma unroll
    for (int j = 0; j < 4; j++) fbA[j] = chunk_off(Tg + lr, ci, j);

    // accumulator ownership: token = t>>2, d-quarter j = t&3 (16 floats)
    const int tok = t >> 2;
    const int dq  = t & 3;
    int roff[4];
    #pragma unroll
    for (int cc = 0; cc < 4; cc++) roff[cc] = chunk_off(tok, cc, dq);

    // av values for this lane's e columns: e = E0 + et*8 + 2ci + {0,1}
    float avv[4][2];
    #pragma unroll
    for (int et = 0; et < 4; et++) {
        avv[et][0] = av[E0 + et * 8 + 2 * ci];
        avv[et][1] = av[E0 + et * 8 + 2 * ci + 1];
    }

    // ---- mbarrier init + first TMA load (current tile) ----
    if (t == 0) {
        mbar_init(mbar0, 1);
        mbar_init(mbar1, 1);
        asm volatile("fence.proxy.async.shared::cta;" ::: "memory");
        mbar_expect_tx(mbar0, TILE_BYTES);
        bulk_ld(stAu, cur + (size_t)n0 * D, mbar0);
    }

    // ---- B fragments = Wq (k-major: b0 = W[e][kc*8+ci], b1 = +4) ----
    uint32_t B[4][8][2];
    #pragma unroll
    for (int et = 0; et < 4; et++) {
        int e = E0 + et * 8 + lr;
        #pragma unroll
        for (int kc = 0; kc < 8; kc++) {
            B[et][kc][0] = f2tf32(Wq[e * 64 + kc * 8 + ci]);
            B[et][kc][1] = f2tf32(Wq[e * 64 + kc * 8 + ci + 4]);
        }
    }

    __syncthreads();                  // mbarrier init visible
    int ph0 = 0, ph1 = 0;
    if (lane == 0) { mbar_wait(mbar0, 0); }
    ph0 = 1;
    __syncthreads();                  // cur staging visible CTA-wide
    transform_tile(stagA, tileU, t, c);
    __syncthreads();                  // tileU ready; stagA free

    // prefetch h=0 (stagA) and h=1 (stagB)
    if (t == 0) {
        mbar_expect_tx(mbar0, TILE_BYTES);
        bulk_ld(stAu, hist + (size_t)n0 * D, mbar0);
        mbar_expect_tx(mbar1, TILE_BYTES);
        bulk_ld(stBu, hist + ((size_t)NTOT + n0) * D, mbar1);
    }

    // ---- Q fragments: C[et] = bias + cur_tile x Wq ; park in qfS ----
    {
        float C0[4], C1[4], C2[4], C3[4];
        #pragma unroll
        for (int et = 0; et < 4; et++) {
            float b0v = bq[E0 + et * 8 + 2 * ci]     + bk[E0 + et * 8 + 2 * ci];
            float b1v = bq[E0 + et * 8 + 2 * ci + 1] + bk[E0 + et * 8 + 2 * ci + 1];
            C0[et] = b0v; C1[et] = b1v; C2[et] = b0v; C3[et] = b1v;
        }
        #pragma unroll
        for (int j = 0; j < 4; j++) {
            uint4 qa = *reinterpret_cast<const uint4*>(&tileU[fbA[j]]);
            uint4 qb = *reinterpret_cast<const uint4*>(&tileU[fbA[j] + 512]);
            #pragma unroll
            for (int et = 0; et < 4; et++) {
                if ((j & 1) == 0) {
                    mma_tf32(C0[et],C1[et],C2[et],C3[et], qa.x,qb.x,qa.y,qb.y,
                             B[et][2*j][0],   B[et][2*j][1]);
                    mma_tf32(C0[et],C1[et],C2[et],C3[et], qa.z,qb.z,qa.w,qb.w,
                             B[et][2*j+1][0], B[et][2*j+1][1]);
                } else {
                    mma_tf32(C0[et],C1[et],C2[et],C3[et], qa.z,qb.z,qa.w,qb.w,
                             B[et][2*j][0],   B[et][2*j][1]);
                    mma_tf32(C0[et],C1[et],C2[et],C3[et], qa.x,qb.x,qa.y,qb.y,
                             B[et][2*j+1][0], B[et][2*j+1][1]);
                }
            }
        }
        #pragma unroll
        for (int et = 0; et < 4; et++)
            qfS[(w * 4 + et) * 32 + lane] = make_float4(C0[et], C1[et], C2[et], C3[et]);
    }

    // ---- swap B fragments to Wk ----
    #pragma unroll
    for (int et = 0; et < 4; et++) {
        int e = E0 + et * 8 + lr;
        #pragma unroll
        for (int kc = 0; kc < 8; kc++) {
            B[et][kc][0] = f2tf32(Wk[e * 64 + kc * 8 + ci]);
            B[et][kc][1] = f2tf32(Wk[e * 64 + kc * 8 + ci + 4]);
        }
    }

    float accR[4][4];
    #pragma unroll
    for (int cc = 0; cc < 4; cc++)
        #pragma unroll
        for (int p = 0; p < 4; p++) accR[cc][p] = 0.f;
    float sreg = 0.f;

    for (int h = 0; h < HTOT; h++) {
        if (lane == 0) {
            if (h & 1) { mbar_wait(mbar1, ph1); } else { mbar_wait(mbar0, ph0); }
        }
        if (h & 1) ph1 ^= 1; else ph0 ^= 1;
        __syncthreads();                 // staging visible; prev RMW done with tileU
        transform_tile((h & 1) ? stagB : stagA, tileU, t, c);
        __syncthreads();                 // tileU ready; staging consumed

        // TMA load for h+2 into the buffer just freed
        if (h + 2 < HTOT && t == 0) {
            uint32_t mb   = (h & 1) ? mbar1 : mbar0;
            uint32_t sdst = (h & 1) ? stBu : stAu;
            mbar_expect_tx(mb, TILE_BYTES);
            bulk_ld(sdst, hist + ((size_t)(h + 2) * NTOT + n0) * D, mb);
        }

        // K-MMA (tokens as A, Wk as B) + tanh-logit
        {
            float C0[4], C1[4], C2[4], C3[4];
            #pragma unroll
            for (int et = 0; et < 4; et++) {
                float4 q4 = qfS[(w * 4 + et) * 32 + lane];
                C0[et] = q4.x; C1[et] = q4.y; C2[et] = q4.z; C3[et] = q4.w;
            }
            #pragma unroll
            for (int j = 0; j < 4; j++) {
                uint4 qa = *reinterpret_cast<const uint4*>(&tileU[fbA[j]]);
                uint4 qb = *reinterpret_cast<const uint4*>(&tileU[fbA[j] + 512]);
                #pragma unroll
                for (int et = 0; et < 4; et++) {
                    if ((j & 1) == 0) {
                        mma_tf32(C0[et],C1[et],C2[et],C3[et], qa.x,qb.x,qa.y,qb.y,
                                 B[et][2*j][0],   B[et][2*j][1]);
                        mma_tf32(C0[et],C1[et],C2[et],C3[et], qa.z,qb.z,qa.w,qb.w,
                                 B[et][2*j+1][0], B[et][2*j+1][1]);
                    } else {
                        mma_tf32(C0[et],C1[et],C2[et],C3[et], qa.z,qb.z,qa.w,qb.w,
                                 B[et][2*j][0],   B[et][2*j][1]);
                        mma_tf32(C0[et],C1[et],C2[et],C3[et], qa.x,qb.x,qa.y,qb.y,
                                 B[et][2*j+1][0], B[et][2*j+1][1]);
                    }
                }
            }
            // logits: rows m = Tg+lr (p_lo) and Tg+lr+8 (p_hi); e = n axis
            float p_lo = 0.f, p_hi = 0.f;
            #pragma unroll
            for (int et = 0; et < 4; et++) {
                float t0 = poly_tanh(C0[et]);
                float t1 = poly_tanh(C1[et]);
                float t2 = poly_tanh(C2[et]);
                float t3 = poly_tanh(C3[et]);
                p_lo = fmaf(t0, avv[et][0], fmaf(t1, avv[et][1], p_lo));
                p_hi = fmaf(t2, avv[et][0], fmaf(t3, avv[et][1], p_hi));
            }
            p_lo += __shfl_xor_sync(0xffffffffu, p_lo, 1);
            p_lo += __shfl_xor_sync(0xffffffffu, p_lo, 2);
            p_hi += __shfl_xor_sync(0xffffffffu, p_hi, 1);
            p_hi += __shfl_xor_sync(0xffffffffu, p_hi, 2);
            if (ci == 0) {
                lp[eh * 128 + Tg + lr]     = p_lo;
                lp[eh * 128 + Tg + lr + 8] = p_hi;
            }
        }
        __syncthreads();                 // logit partials ready

        // softmax accumulation + register RMW (tileU valid until next transform)
        float L  = lp[tok] + lp[128 + tok];
        float pe = __expf(L);            // logits bounded << 88
        sreg += pe;
        #pragma unroll
        for (int cc = 0; cc < 4; cc++) {
            float4 t4 = *reinterpret_cast<const float4*>(&tileU[roff[cc]]);
            accR[cc][0] = fmaf(pe, t4.x, accR[cc][0]);
            accR[cc][1] = fmaf(pe, t4.y, accR[cc][1]);
            accR[cc][2] = fmaf(pe, t4.z, accR[cc][2]);
            accR[cc][3] = fmaf(pe, t4.w, accR[cc][3]);
        }
    }

    // ---- epilogue: ws = acc/s ; context = tanh(sc*|ws|/2)/(sc*|ws|) * ws ----
    float sinv = __fdividef(1.f, sreg);
    float ssq = 0.f;
    #pragma unroll
    for (int cc = 0; cc < 4; cc++)
        #pragma unroll
        for (int p = 0; p < 4; p++)
            ssq = fmaf(accR[cc][p], accR[cc][p], ssq);
    ssq += __shfl_xor_sync(0xffffffffu, ssq, 1);
    ssq += __shfl_xor_sync(0xffffffffu, ssq, 2);

    float r = sqrtf(ssq) * sinv;
    float u = sc * r;
    float g;
    if (u > 1e-12f) {
        float e = __expf(u);
        g = __fdividef(e - 1.f, (e + 1.f) * u);    // tanh(u/2)/u
    } else {
        g = 0.5f;
    }
    float f = g * sinv;

    const int xo = (dq & 1) << 1;        // posP = posR ^ ((j&1)<<1)
    float4* op = reinterpret_cast<float4*>(out + (size_t)(n0 + tok) * D + dq * 16);
    #pragma unroll
    for (int gi = 0; gi < 4; gi++) {
        int pos = gi ^ xo;
        float4 o;
        o.x = accR[0][pos] * f;
        o.y = accR[1][pos] * f;
        o.z = accR[2][pos] * f;
        o.w = accR[3][pos] * f;
        op[gi] = o;
    }
}

extern "C" void kernel_launch(void* const* d_in, const int* in_sizes, int n_in,
                              void* d_out, int out_size) {
    const float* cur  = (const float*)d_in[0];
    const float* hist = (const float*)d_in[1];
    const float* curv = (const float*)d_in[2];
    const float* Wq   = (const float*)d_in[3];
    const float* bq   = (const float*)d_in[4];
    const float* Wk   = (const float*)d_in[5];
    const float* bk   = (const float*)d_in[6];
    const float* av   = (const float*)d_in[7];
    float* o = (float*)d_out;

    const int smem_bytes = (8192 * 4 + 256 + 16) * sizeof(float);
    cudaFuncSetAttribute(hyp_attn_kernel,
                         cudaFuncAttributeMaxDynamicSharedMemorySize, smem_bytes);
    hyp_attn_kernel<<<NTOT / NT, NTHREADS, smem_bytes>>>(
        cur, hist, curv, Wq, bq, Wk, bk, av, o);
}

// round 10
// speedup vs baseline: 1.0536x; 1.0536x over previous
#include <cuda_runtime.h>
#include <math.h>
#include <stdint.h>

#define NTOT 32768
#define HTOT 32
#define D    64
#define NT   128
#define NTHREADS 512
#define TILE_BYTES (NT * D * 4)   // 32768

// ---------- tf32 helpers ----------
__device__ __forceinline__ uint32_t f2tf32(float f) {
    uint32_t u;
    asm("cvt.rna.tf32.f32 %0, %1;" : "=r"(u) : "f"(f));
    return u;
}

__device__ __forceinline__ void mma_tf32(float& c0, float& c1, float& c2, float& c3,
                                         uint32_t a0, uint32_t a1, uint32_t a2, uint32_t a3,
                                         uint32_t b0, uint32_t b1) {
    asm volatile(
        "mma.sync.aligned.m16n8k8.row.col.f32.tf32.tf32.f32 "
        "{%0,%1,%2,%3}, {%4,%5,%6,%7}, {%8,%9}, {%0,%1,%2,%3};"
        : "+f"(c0), "+f"(c1), "+f"(c2), "+f"(c3)
        : "r"(a0), "r"(a1), "r"(a2), "r"(a3), "r"(b0), "r"(b1));
}

__device__ __forceinline__ float poly_tanh(float x) {
    float t = x * x;
    float p = fmaf(t, -0.05396825397f, 0.13333333333f);
    p = fmaf(t, p, -0.33333333333f);
    return fmaf(x * t, p, x);
}

__device__ __forceinline__ float logscale_from_ssq(float ssq, float c) {
    float t = c * ssq;
    float p = fmaf(t, 0.22222222f, 0.28571429f);
    p = fmaf(t, p, 0.4f);
    p = fmaf(t, p, 0.66666667f);
    return fmaf(t, p, 2.0f);
}

// Fragment-native swizzled tile layout (conflict-free; rounds 3-8).
__device__ __forceinline__ int chunk_off(int token, int ci, int j) {
    int pb = (token >> 1) & 1;
    int b2 = (token >> 2) & 1;
    int jl = j & 1;
    int j1 = (j >> 1) & 1;
    int slot = ((token & 1) << 2) | (ci ^ (jl ^ pb) ^ ((j1 ^ b2) << 1));
    return ((token >> 1) << 7) | (j << 5) | (slot << 2);
}

// ---------- TMA bulk copy + mbarrier ----------
__device__ __forceinline__ void mbar_init(uint32_t mbar, uint32_t cnt) {
    asm volatile("mbarrier.init.shared.b64 [%0], %1;" :: "r"(mbar), "r"(cnt) : "memory");
}
__device__ __forceinline__ void mbar_expect_tx(uint32_t mbar, uint32_t bytes) {
    asm volatile("mbarrier.arrive.expect_tx.shared.b64 _, [%0], %1;"
                 :: "r"(mbar), "r"(bytes) : "memory");
}
__device__ __forceinline__ void bulk_ld(uint32_t sdst, const void* gsrc, uint32_t mbar) {
    asm volatile(
        "cp.async.bulk.shared::cta.global.mbarrier::complete_tx::bytes [%0], [%1], %2, [%3];"
        :: "r"(sdst), "l"(gsrc), "r"((uint32_t)TILE_BYTES), "r"(mbar) : "memory");
}
__device__ __forceinline__ void mbar_wait(uint32_t mbar, uint32_t parity) {
    uint32_t done;
    asm volatile(
        "{\n\t.reg .pred p;\n\t"
        "mbarrier.try_wait.parity.acquire.cta.shared::cta.b64 p, [%1], %2;\n\t"
        "selp.b32 %0, 1, 0, p;\n\t}"
        : "=r"(done) : "r"(mbar), "r"(parity) : "memory");
    if (!done) {
        asm volatile(
            "{\n\t.reg .pred P1;\n\t"
            "WAIT_LOOP_%=:\n\t"
            "mbarrier.try_wait.parity.acquire.cta.shared::cta.b64 P1, [%0], %1, 0x989680;\n\t"
            "@P1 bra.uni WAIT_DONE_%=;\n\t"
            "bra.uni WAIT_LOOP_%=;\n\t"
            "WAIT_DONE_%=:\n\t}"
            :: "r"(mbar), "r"(parity) : "memory");
    }
}

#define BAR_CONS() asm volatile("bar.sync 1, 256;" ::: "memory")
#define BAR_PROD() asm volatile("bar.sync 2, 256;" ::: "memory")

// producer transform: 256 threads, each handles 32 elements (rows rgrp+16*jj)
__device__ __forceinline__ void transform_tile_p(const float* __restrict__ stag,
                                                 uint32_t* __restrict__ tileU,
                                                 int pt, float c) {
    const float4* s4 = reinterpret_cast<const float4*>(stag);
    const int col4 = pt & 15;
    const int rgrp = pt >> 4;         // 0..15
    const int j    = col4 >> 2;
    const int posR = col4 & 3;
    const int posP = posR ^ ((j & 1) << 1);
    int base[4];
    #pragma unroll
    for (int ci = 0; ci < 4; ci++)
        base[ci] = chunk_off(rgrp, ci, j) + posP;

    #pragma unroll
    for (int jj = 0; jj < 8; jj++) {
        float4 v = s4[pt + 256 * jj];
        float s = fmaf(v.x, v.x, fmaf(v.y, v.y, fmaf(v.z, v.z, v.w * v.w)));
        #pragma unroll
        for (int off = 1; off < 16; off <<= 1)
            s += __shfl_xor_sync(0xffffffffu, s, off);
        float sc = logscale_from_ssq(s, c);
        int o = jj << 10;             // +16 rows = +1024 floats
        tileU[base[0] + o] = f2tf32(v.x * sc);
        tileU[base[1] + o] = f2tf32(v.y * sc);
        tileU[base[2] + o] = f2tf32(v.z * sc);
        tileU[base[3] + o] = f2tf32(v.w * sc);
    }
}

__global__ __launch_bounds__(NTHREADS, 1)
void hyp_attn_kernel(const float* __restrict__ cur,
                     const float* __restrict__ hist,
                     const float* __restrict__ curv,
                     const float* __restrict__ Wq,
                     const float* __restrict__ bq,
                     const float* __restrict__ Wk,
                     const float* __restrict__ bk,
                     const float* __restrict__ av,
                     float* __restrict__ out) {
    extern __shared__ float sm[];
    uint32_t* tile0 = reinterpret_cast<uint32_t*>(sm);            // 8192 u32
    uint32_t* tile1 = reinterpret_cast<uint32_t*>(sm) + 8192;     // 8192 u32
    float* stagA = sm + 16384;                                    // 8192
    float* stagB = sm + 24576;                                    // 8192
    float4* qfS  = reinterpret_cast<float4*>(sm + 32768);         // 2048 float4
    float* lp    = sm + 40960;                                    // 512
    uint32_t mbarBase = (uint32_t)__cvta_generic_to_shared(sm + 41472);

    const int t    = threadIdx.x;
    const int lane = t & 31;
    const int w    = t >> 5;          // 0..15
    const int n0   = blockIdx.x * NT;
    const float c  = curv[0];
    const float sc = sqrtf(c);
    const bool isCons = (w < 8);

    const uint32_t mbar0 = mbarBase;
    const uint32_t mbar1 = mbarBase + 8;
    const uint32_t stAu = (uint32_t)__cvta_generic_to_shared(stagA);
    const uint32_t stBu = (uint32_t)__cvta_generic_to_shared(stagB);

    // ---- TMA: first load (current tile) ----
    if (t == 256) {
        mbar_init(mbar0, 1);
        mbar_init(mbar1, 1);
        asm volatile("fence.proxy.async.shared::cta;" ::: "memory");
        mbar_expect_tx(mbar0, TILE_BYTES);
        bulk_ld(stAu, cur + (size_t)n0 * D, mbar0);
    }

    // =================== consumer-side setup ===================
    // consumer warp w: e-quarter eq = w&3, token half th = w>>2
    const int eq = w & 3;
    const int th = (w >> 2) & 1;
    const int Th = th * 64;
    const int lr = lane >> 2;
    const int ci = lane & 3;
    const int r0 = eq * 16 + lr;

    int fb[4];
    #pragma unroll
    for (int j = 0; j < 4; j++) fb[j] = chunk_off(Th + lr, ci, j);

    uint32_t A[8][4];
    float av0 = 0.f, av1 = 0.f;
    if (isCons) {
        av0 = av[r0];
        av1 = av[r0 + 8];
        #pragma unroll
        for (int kc = 0; kc < 8; kc++) {
            A[kc][0] = f2tf32(Wq[r0 * 64 + kc * 8 + ci]);
            A[kc][1] = f2tf32(Wq[(r0 + 8) * 64 + kc * 8 + ci]);
            A[kc][2] = f2tf32(Wq[r0 * 64 + kc * 8 + ci + 4]);
            A[kc][3] = f2tf32(Wq[(r0 + 8) * 64 + kc * 8 + ci + 4]);
        }
    }

    // consumer RMW ownership (256 consumer threads): token = t>>1, d-half = t&1
    const int tok = t >> 1;           // valid for t<256
    const int hh  = t & 1;
    int roff[2][4];
    #pragma unroll
    for (int jj = 0; jj < 2; jj++)
        #pragma unroll
        for (int cc = 0; cc < 4; cc++)
            roff[jj][cc] = chunk_off(tok & 127, cc, 2 * hh + jj);

    const int pt = t - 256;           // producer thread id 0..255

    __syncthreads();                  // mbar init visible

    // ---- producers transform cur -> tile0 ----
    if (!isCons) {
        mbar_wait(mbar0, 0);
        transform_tile_p(stagA, tile0, pt, c);
    }
    __syncthreads();                  // tile0 (cur) ready; stagA free

    if (t == 256) {                   // stage h0, h1
        mbar_expect_tx(mbar0, TILE_BYTES);
        bulk_ld(stAu, hist + (size_t)n0 * D, mbar0);
        mbar_expect_tx(mbar1, TILE_BYTES);
        bulk_ld(stBu, hist + ((size_t)NTOT + n0) * D, mbar1);
    }

    // ---- consumers: Q fragments from tile0 -> qfS; producers: wait h0 ----
    if (isCons) {
        float b0v = bq[r0]     + bk[r0];
        float b1v = bq[r0 + 8] + bk[r0 + 8];
        #pragma unroll
        for (int nc = 0; nc < 8; nc++) {
            float c0 = b0v, c1 = b0v, c2 = b1v, c3 = b1v;
            #pragma unroll
            for (int j = 0; j < 4; j++) {
                uint4 q = *reinterpret_cast<const uint4*>(&tile0[fb[j] + nc * 512]);
                if ((j & 1) == 0) {
                    mma_tf32(c0,c1,c2,c3, A[2*j][0],A[2*j][1],A[2*j][2],A[2*j][3], q.x, q.y);
                    mma_tf32(c0,c1,c2,c3, A[2*j+1][0],A[2*j+1][1],A[2*j+1][2],A[2*j+1][3], q.z, q.w);
                } else {
                    mma_tf32(c0,c1,c2,c3, A[2*j][0],A[2*j][1],A[2*j][2],A[2*j][3], q.z, q.w);
                    mma_tf32(c0,c1,c2,c3, A[2*j+1][0],A[2*j+1][1],A[2*j+1][2],A[2*j+1][3], q.x, q.y);
                }
            }
            qfS[(w * 8 + nc) * 32 + lane] = make_float4(c0, c1, c2, c3);
        }
        // swap A fragments to Wk
        #pragma unroll
        for (int kc = 0; kc < 8; kc++) {
            A[kc][0] = f2tf32(Wk[r0 * 64 + kc * 8 + ci]);
            A[kc][1] = f2tf32(Wk[(r0 + 8) * 64 + kc * 8 + ci]);
            A[kc][2] = f2tf32(Wk[r0 * 64 + kc * 8 + ci + 4]);
            A[kc][3] = f2tf32(Wk[(r0 + 8) * 64 + kc * 8 + ci + 4]);
        }
    } else {
        mbar_wait(mbar0, 1);          // h0 staged
    }
    __syncthreads();                  // consumers done with tile0; h0 in stagA

    // ---- producers transform h0 -> tile0, then stage h2 ----
    if (!isCons) {
        transform_tile_p(stagA, tile0, pt, c);
        BAR_PROD();                   // all producers done reading stagA
        if (t == 256) {
            mbar_expect_tx(mbar0, TILE_BYTES);
            bulk_ld(stAu, hist + ((size_t)2 * NTOT + n0) * D, mbar0);
        }
    }
    __syncthreads();                  // tile0 = h0 transformed

    float accR[2][4][4];
    #pragma unroll
    for (int jj = 0; jj < 2; jj++)
        #pragma unroll
        for (int cc = 0; cc < 4; cc++)
            #pragma unroll
            for (int p = 0; p < 4; p++) accR[jj][cc][p] = 0.f;
    float sreg = 0.f;

    int ph0 = 0, ph1 = 0;             // next-wait parities: mbar0->h2, mbar1->h1

    for (int h = 0; h < HTOT; h++) {
        const uint32_t* tU = (h & 1) ? tile1 : tile0;

        if (isCons) {
            // K-MMA + tanh-logit on tile h (64 tokens, one e-quarter)
            #pragma unroll
            for (int nc = 0; nc < 8; nc++) {
                float4 q4 = qfS[(w * 8 + nc) * 32 + lane];
                float c0 = q4.x, c1 = q4.y, c2 = q4.z, c3 = q4.w;
                #pragma unroll
                for (int j = 0; j < 4; j++) {
                    uint4 q = *reinterpret_cast<const uint4*>(&tU[fb[j] + nc * 512]);
                    if ((j & 1) == 0) {
                        mma_tf32(c0,c1,c2,c3, A[2*j][0],A[2*j][1],A[2*j][2],A[2*j][3], q.x, q.y);
                        mma_tf32(c0,c1,c2,c3, A[2*j+1][0],A[2*j+1][1],A[2*j+1][2],A[2*j+1][3], q.z, q.w);
                    } else {
                        mma_tf32(c0,c1,c2,c3, A[2*j][0],A[2*j][1],A[2*j][2],A[2*j][3], q.z, q.w);
                        mma_tf32(c0,c1,c2,c3, A[2*j+1][0],A[2*j+1][1],A[2*j+1][2],A[2*j+1][3], q.x, q.y);
                    }
                }
                float t0 = poly_tanh(c0);
                float t1 = poly_tanh(c1);
                float t2 = poly_tanh(c2);
                float t3 = poly_tanh(c3);
                float p0 = fmaf(t0, av0, t2 * av1);
                float p1 = fmaf(t1, av0, t3 * av1);
                #pragma unroll
                for (int off = 4; off < 32; off <<= 1) {
                    p0 += __shfl_xor_sync(0xffffffffu, p0, off);
                    p1 += __shfl_xor_sync(0xffffffffu, p1, off);
                }
                if (lane < 4) {
                    float2 st; st.x = p0; st.y = p1;
                    *reinterpret_cast<float2*>(&lp[eq * 128 + Th + nc * 8 + 2 * lane]) = st;
                }
            }
            BAR_CONS();               // logit partials ready (consumer scope)

            float L  = lp[tok] + lp[128 + tok] + lp[256 + tok] + lp[384 + tok];
            float pe = __expf(L);     // logits bounded << 88
            sreg += pe;
            #pragma unroll
            for (int jj = 0; jj < 2; jj++)
                #pragma unroll
                for (int cc = 0; cc < 4; cc++) {
                    float4 t4 = *reinterpret_cast<const float4*>(&tU[roff[jj][cc]]);
                    accR[jj][cc][0] = fmaf(pe, t4.x, accR[jj][cc][0]);
                    accR[jj][cc][1] = fmaf(pe, t4.y, accR[jj][cc][1]);
                    accR[jj][cc][2] = fmaf(pe, t4.z, accR[jj][cc][2]);
                    accR[jj][cc][3] = fmaf(pe, t4.w, accR[jj][cc][3]);
                }
        } else {
            // producer: transform tile h+1 while consumers work on h
            if (h + 1 < HTOT) {
                if ((h + 1) & 1) { mbar_wait(mbar1, ph1); ph1 ^= 1; }
                else             { mbar_wait(mbar0, ph0); ph0 ^= 1; }
                const float* stg = ((h + 1) & 1) ? stagB : stagA;
                uint32_t* tDst   = ((h + 1) & 1) ? tile1 : tile0;
                transform_tile_p(stg, tDst, pt, c);
                BAR_PROD();           // staging[(h+1)&1] fully consumed
                if (t == 256 && h + 3 < HTOT) {
                    uint32_t mb   = ((h + 1) & 1) ? mbar1 : mbar0;
                    uint32_t sdst = ((h + 1) & 1) ? stBu : stAu;
                    mbar_expect_tx(mb, TILE_BYTES);
                    bulk_ld(sdst, hist + ((size_t)(h + 3) * NTOT + n0) * D, mb);
                }
            }
        }
        __syncthreads();              // handoff: tile h+1 ready; tile h released
    }

    // ---- epilogue (consumers only) ----
    if (isCons) {
        float sinv = __fdividef(1.f, sreg);
        float ssq = 0.f;
        #pragma unroll
        for (int jj = 0; jj < 2; jj++)
            #pragma unroll
            for (int cc = 0; cc < 4; cc++)
                #pragma unroll
                for (int p = 0; p < 4; p++)
                    ssq = fmaf(accR[jj][cc][p], accR[jj][cc][p], ssq);
        ssq += __shfl_xor_sync(0xffffffffu, ssq, 1);   // combine d-halves

        float r = sqrtf(ssq) * sinv;
        float u = sc * r;
        float g;
        if (u > 1e-12f) {
            float e = __expf(u);
            g = __fdividef(e - 1.f, (e + 1.f) * u);    // tanh(u/2)/u
        } else {
            g = 0.5f;
        }
        float f = g * sinv;

        float4* op = reinterpret_cast<float4*>(out + (size_t)(n0 + tok) * D + hh * 32);
        #pragma unroll
        for (int gi = 0; gi < 8; gi++) {
            int jj  = gi >> 2;
            int pos = (gi & 3) ^ (jj << 1);
            float4 o;
            o.x = accR[jj][0][pos] * f;
            o.y = accR[jj][1][pos] * f;
            o.z = accR[jj][2][pos] * f;
            o.w = accR[jj][3][pos] * f;
            op[gi] = o;
        }
    }
}

extern "C" void kernel_launch(void* const* d_in, const int* in_sizes, int n_in,
                              void* d_out, int out_size) {
    const float* cur  = (const float*)d_in[0];
    const float* hist = (const float*)d_in[1];
    const float* curv = (const float*)d_in[2];
    const float* Wq   = (const float*)d_in[3];
    const float* bq   = (const float*)d_in[4];
    const float* Wk   = (const float*)d_in[5];
    const float* bk   = (const float*)d_in[6];
    const float* av   = (const float*)d_in[7];
    float* o = (float*)d_out;

    const int smem_bytes = (41472 + 16) * sizeof(float);
    cudaFuncSetAttribute(hyp_attn_kernel,
                         cudaFuncAttributeMaxDynamicSharedMemorySize, smem_bytes);
    hyp_attn_kernel<<<NTOT / NT, NTHREADS, smem_bytes>>>(
        cur, hist, curv, Wq, bq, Wk, bk, av, o);
}